// round 2
// baseline (speedup 1.0000x reference)
#include <cuda_runtime.h>
#include <cuda_bf16.h>

// SeriesDecompEMA: x[B,T,C] f32, alpha scalar f32.
// ma[0] = x[0]; ma[t] = (1-a)*ma[t-1] + a*x[t]  (exact telescoping of the
// reference's cumsum/divisor form). out = concat(res = x - ma, ma).
// Recurrence in double to match the reference's float64 accumulation.

#define EMA_B 64
#define EMA_T 720
#define EMA_C 512

__global__ __launch_bounds__(64) void ema_decomp_kernel(
    const float* __restrict__ x,
    const float* __restrict__ alpha_p,
    float* __restrict__ res,
    float* __restrict__ ma)
{
    const int idx = blockIdx.x * 64 + threadIdx.x;   // 0 .. B*C-1
    const int b = idx >> 9;          // / 512
    const int c = idx & 511;         // % 512

    const size_t off = (size_t)b * ((size_t)EMA_T * EMA_C) + (size_t)c;
    const float* __restrict__ xp = x + off;
    float* __restrict__ rp = res + off;
    float* __restrict__ mp = ma + off;

    const double a  = (double)__ldg(alpha_p);
    const double om = 1.0 - a;

    // t = 0: ma = x0 exactly, res = 0 exactly (matches reference).
    const float x0 = __ldg(xp);
    double m = (double)x0;
    mp[0] = x0;
    rp[0] = 0.0f;

    constexpr int P = 16;   // prefetch depth (MLP for DRAM latency hiding)
    float buf[P];
    float nxt[P];

    int t = 1;
    #pragma unroll
    for (int i = 0; i < P; ++i)
        buf[i] = xp[(size_t)(t + i) * EMA_C];

    while (t + P <= EMA_T) {
        const int tn = t + P;
        // Prefetch next group (independent of the fma chain; ptxas front-batches
        // these LDGs, giving ~16 outstanding loads per warp).
        if (tn + P <= EMA_T) {
            #pragma unroll
            for (int i = 0; i < P; ++i)
                nxt[i] = xp[(size_t)(tn + i) * EMA_C];
        }
        #pragma unroll
        for (int i = 0; i < P; ++i) {
            const double xv = (double)buf[i];
            m = fma(om, m, a * xv);
            const float mf = (float)m;
            mp[(size_t)(t + i) * EMA_C] = mf;
            rp[(size_t)(t + i) * EMA_C] = buf[i] - mf;
        }
        #pragma unroll
        for (int i = 0; i < P; ++i) buf[i] = nxt[i];
        t = tn;
    }

    // Tail (719 = 44*16 + 15 remaining after t=1 start)
    for (; t < EMA_T; ++t) {
        const float xv = xp[(size_t)t * EMA_C];
        m = fma(om, m, a * (double)xv);
        const float mf = (float)m;
        mp[(size_t)t * EMA_C] = mf;
        rp[(size_t)t * EMA_C] = xv - mf;
    }
}

extern "C" void kernel_launch(void* const* d_in, const int* in_sizes, int n_in,
                              void* d_out, int out_size)
{
    const float* x       = (const float*)d_in[0];
    const float* alpha_p = (const float*)d_in[1];
    float* out = (float*)d_out;

    const size_t plane = (size_t)EMA_B * EMA_T * EMA_C;  // B*T*C
    float* res = out;           // first output: x - ma
    float* ma  = out + plane;   // second output: ma

    const int total = EMA_B * EMA_C;          // 32768 threads
    const int block = 64;
    const int grid  = total / block;          // 512 blocks

    ema_decomp_kernel<<<grid, block>>>(x, alpha_p, res, ma);
}